// round 9
// baseline (speedup 1.0000x reference)
#include <cuda_runtime.h>
#include <cuda.h>
#include <cuda_fp16.h>
#include <cstdint>

#define BDIM 4096
#define DDIM 1024
#define KSEL 1024
#define MARGIN 0.5f
#define EPSV 1e-6f
#define CEPS (1024.0f * 1e-6f * 1e-6f)   /* D * eps^2 */
#define SCALE (1.0f / (4096.0f * 1024.0f))
#define NBINS 4096
#define QPOW 1048576.0f                  /* 2^20 sum quantizer */
#define QINV (1.0f / 1048576.0f)

// GEMM tiling: block 128x128, BK=64 halves, 128 threads (4 warps of 64x64)
#define GM 128
#define GN 128
#define BK 64
#define NKT (DDIM / BK)              /* 16 */
#define TILE_B 16384                 /* 128 rows x 128B (fp16, SW128) */
#define OFF_B TILE_B
#define STAGE_B (2 * TILE_B)         /* 32768 */
#define NSTAGE 3
#define SM_BUF0 1024
#define GSMEM (SM_BUF0 + NSTAGE * STAGE_B)   /* 99328 */
#define STAGE_TX 32768u
#define CSTR 132                     /* epilogue transpose-stage stride (floats) */

// ---------------- device scratch (static: no allocations allowed) ----------
__device__ float g_dist[(size_t)BDIM * BDIM];
__device__ float g_distT[(size_t)BDIM * BDIM];
__device__ float g_a[BDIM];   // ||x||^2 + 2*eps*sum(x)
__device__ float g_b[BDIM];   // ||y||^2 - 2*eps*sum(y)
__device__ __half g_xh[(size_t)BDIM * DDIM];
__device__ __half g_yh[(size_t)BDIM * DDIM];

// ---------------- helpers --------------------------------------------------
__device__ __forceinline__ uint32_t smem_u32(const void* p) {
    return (uint32_t)__cvta_generic_to_shared(p);
}
__device__ __forceinline__ void mbar_init(uint32_t m, uint32_t cnt) {
    asm volatile("mbarrier.init.shared.b64 [%0], %1;" :: "r"(m), "r"(cnt) : "memory");
}
__device__ __forceinline__ void mbar_expect(uint32_t m, uint32_t bytes) {
    asm volatile("mbarrier.arrive.expect_tx.shared.b64 _, [%0], %1;"
                 :: "r"(m), "r"(bytes) : "memory");
}
__device__ __forceinline__ void mbar_wait(uint32_t m, uint32_t ph) {
    asm volatile(
        "{\n\t.reg .pred P;\n"
        "W%=:\n\t"
        "mbarrier.try_wait.parity.acquire.cta.shared::cta.b64 P, [%0], %1, 0x989680;\n\t"
        "@P bra D%=;\n\t"
        "bra W%=;\n"
        "D%=:\n\t}"
        :: "r"(m), "r"(ph) : "memory");
}
__device__ __forceinline__ void tma2d(uint32_t dst, const CUtensorMap* map,
                                      int cx, int cy, uint32_t mbar) {
    asm volatile(
        "cp.async.bulk.tensor.2d.shared::cluster.global.tile.mbarrier::complete_tx::bytes "
        "[%0], [%1, {%2, %3}], [%4];"
        :: "r"(dst), "l"(map), "r"(cx), "r"(cy), "r"(mbar) : "memory");
}
__device__ __forceinline__ void ldsm4(uint32_t& r0, uint32_t& r1, uint32_t& r2,
                                      uint32_t& r3, uint32_t addr) {
    asm volatile(
        "ldmatrix.sync.aligned.m8n8.x4.shared.b16 {%0,%1,%2,%3}, [%4];"
        : "=r"(r0), "=r"(r1), "=r"(r2), "=r"(r3) : "r"(addr));
}
__device__ __forceinline__ void mma_f16(float* c, uint32_t a0, uint32_t a1,
                                        uint32_t a2, uint32_t a3,
                                        uint32_t b0, uint32_t b1) {
    asm volatile(
        "mma.sync.aligned.m16n8k16.row.col.f32.f16.f16.f32 "
        "{%0,%1,%2,%3}, {%4,%5,%6,%7}, {%8,%9}, {%0,%1,%2,%3};"
        : "+f"(c[0]), "+f"(c[1]), "+f"(c[2]), "+f"(c[3])
        : "r"(a0), "r"(a1), "r"(a2), "r"(a3), "r"(b0), "r"(b1));
}

// ---------------- small kernels -------------------------------------------
__global__ void zero_out_kernel(float* out) {
    if (threadIdx.x == 0) { out[0] = 0.f; out[1] = 0.f; }
}

// fused: row stats (a/b vectors) + fp32->fp16 conversion, one read of X/Y
__global__ __launch_bounds__(256)
void rowconv_kernel(const float* __restrict__ X, const float* __restrict__ Y) {
    __shared__ float r1s[8], r2s[8];
    const int r = blockIdx.x, which = blockIdx.y, tid = threadIdx.x;
    const float* p = (which ? Y : X) + (size_t)r * DDIM;
    __half* q = (which ? g_yh : g_xh) + (size_t)r * DDIM;

    float4 v = ((const float4*)p)[tid];
    __half h[4] = {__float2half_rn(v.x), __float2half_rn(v.y),
                   __float2half_rn(v.z), __float2half_rn(v.w)};
    ((uint2*)q)[tid] = *(uint2*)h;

    float s1 = v.x + v.y + v.z + v.w;
    float s2 = v.x * v.x + v.y * v.y + v.z * v.z + v.w * v.w;
    for (int o = 16; o; o >>= 1) {
        s1 += __shfl_down_sync(0xffffffffu, s1, o);
        s2 += __shfl_down_sync(0xffffffffu, s2, o);
    }
    int lane = tid & 31, w = tid >> 5;
    if (lane == 0) { r1s[w] = s1; r2s[w] = s2; }
    __syncthreads();
    if (tid == 0) {
        s1 = 0.f; s2 = 0.f;
        for (int i = 0; i < 8; i++) { s1 += r1s[i]; s2 += r2s[i]; }
        if (which == 0) g_a[r] = s2 + 2.f * EPSV * s1;
        else            g_b[r] = s2 - 2.f * EPSV * s1;
    }
}

// ---------------- fp16 mma.sync GEMM + fused transpose --------------------
// TMA 2D fp16 tiles (SW128), ldmatrix.x4 fragments, m16n8k16 f16 MMA.
// 3-stage pipeline, prefetch distance 3.
__global__ __launch_bounds__(128, 2)
void gemm_dist_kernel(const __grid_constant__ CUtensorMap tmx,
                      const __grid_constant__ CUtensorMap tmy) {
    extern __shared__ char smem[];
    const uint32_t sb = smem_u32(smem);
    const int tid  = threadIdx.x;
    const int lane = tid & 31, wid = tid >> 5;
    const int wm = wid & 1, wn = wid >> 1;   // 2x2 warp grid, 64x64 each
    const int g  = lane >> 2, tg = lane & 3;
    const int m0 = blockIdx.y * GM, n0 = blockIdx.x * GN;

    // per-lane ldmatrix addressing (SW128: row r XORs (r&7)*16 into col bytes)
    const int row_in = lane & 7;
    const uint32_t rowx = (uint32_t)row_in * 16;
    const int a_half = (lane >> 3) & 1;
    const int a_kseg = lane >> 4;
    const int quad   = lane >> 3;
    const int b_radd = (quad >> 1) * 8;
    const int b_kseg = quad & 1;
    uint32_t arow[4], brow[4];
#pragma unroll
    for (int mt = 0; mt < 4; mt++)
        arow[mt] = (uint32_t)(wm * 64 + mt * 16 + row_in + 8 * a_half) * 128;
#pragma unroll
    for (int p = 0; p < 4; p++)
        brow[p] = (uint32_t)(wn * 64 + p * 16 + row_in + b_radd) * 128;

    if (tid == 0)
        for (int s = 0; s < NSTAGE; s++) mbar_init(sb + 16 * s, 1);
    __syncthreads();

    float acc[4][8][4];
#pragma unroll
    for (int mt = 0; mt < 4; mt++)
#pragma unroll
        for (int nt = 0; nt < 8; nt++)
#pragma unroll
            for (int q = 0; q < 4; q++) acc[mt][nt][q] = 0.f;

#define LOAD_STAGE(KT)                                                        \
    if (tid == 0) {                                                           \
        int _s = (KT) % NSTAGE;                                               \
        uint32_t _mb = sb + 16 * _s;                                          \
        uint32_t _buf = sb + SM_BUF0 + (uint32_t)_s * STAGE_B;                \
        mbar_expect(_mb, STAGE_TX);                                           \
        tma2d(_buf, &tmx, (KT) * BK, m0, _mb);                                \
        tma2d(_buf + OFF_B, &tmy, (KT) * BK, n0, _mb);                        \
    }

    LOAD_STAGE(0);
    LOAD_STAGE(1);
    LOAD_STAGE(2);

    for (int kt = 0; kt < NKT; kt++) {
        const int st = kt % NSTAGE;
        mbar_wait(sb + 16 * st, (kt / NSTAGE) & 1);

        const uint32_t abuf = sb + SM_BUF0 + (uint32_t)st * STAGE_B;
        const uint32_t bbuf = abuf + OFF_B;

#pragma unroll
        for (int s = 0; s < 4; s++) {
            const uint32_t offa = ((uint32_t)(s * 32 + a_kseg * 16)) ^ rowx;
            const uint32_t offb = ((uint32_t)(s * 32 + b_kseg * 16)) ^ rowx;
            uint32_t A0[4], A1[4], A2[4], A3[4];
#pragma unroll
            for (int mt = 0; mt < 4; mt++)
                ldsm4(A0[mt], A1[mt], A2[mt], A3[mt], abuf + arow[mt] + offa);
            uint32_t B0[8], B1[8];
#pragma unroll
            for (int p = 0; p < 4; p++)
                ldsm4(B0[2 * p], B1[2 * p], B0[2 * p + 1], B1[2 * p + 1],
                      bbuf + brow[p] + offb);
#pragma unroll
            for (int nt = 0; nt < 8; nt++) {
                mma_f16(acc[0][nt], A0[0], A1[0], A2[0], A3[0], B0[nt], B1[nt]);
                mma_f16(acc[1][nt], A0[1], A1[1], A2[1], A3[1], B0[nt], B1[nt]);
                mma_f16(acc[2][nt], A0[2], A1[2], A2[2], A3[2], B0[nt], B1[nt]);
                mma_f16(acc[3][nt], A0[3], A1[3], A2[3], A3[3], B0[nt], B1[nt]);
            }
        }
        __syncthreads();                 // all warps done reading this buffer
        if (kt + 3 < NKT) LOAD_STAGE(kt + 3);
    }

    // epilogue: distances; direct write to g_dist, smem-staged for g_distT
    float* Csh = (float*)smem;
#pragma unroll
    for (int mt = 0; mt < 4; mt++) {
        int r0 = wm * 64 + mt * 16 + g;
        float a0 = g_a[m0 + r0] + CEPS;
        float a1 = g_a[m0 + r0 + 8] + CEPS;
#pragma unroll
        for (int nt = 0; nt < 8; nt++) {
            int c = wn * 64 + nt * 8 + 2 * tg;
            float b0 = g_b[n0 + c], b1 = g_b[n0 + c + 1];
            float* a4 = acc[mt][nt];
            float o00 = sqrtf(fmaxf(a0 + b0 - 2.f * a4[0], 0.f));
            float o01 = sqrtf(fmaxf(a0 + b1 - 2.f * a4[1], 0.f));
            float o10 = sqrtf(fmaxf(a1 + b0 - 2.f * a4[2], 0.f));
            float o11 = sqrtf(fmaxf(a1 + b1 - 2.f * a4[3], 0.f));
            *(float2*)&g_dist[(size_t)(m0 + r0) * BDIM + n0 + c] =
                make_float2(o00, o01);
            *(float2*)&g_dist[(size_t)(m0 + r0 + 8) * BDIM + n0 + c] =
                make_float2(o10, o11);
            Csh[c * CSTR + r0]           = o00;
            Csh[(c + 1) * CSTR + r0]     = o01;
            Csh[c * CSTR + r0 + 8]       = o10;
            Csh[(c + 1) * CSTR + r0 + 8] = o11;
        }
    }
    __syncthreads();
#pragma unroll
    for (int i = tid; i < 128 * 32; i += 128) {
        int j = i >> 5, q = i & 31;
        float4 v = *(float4*)&Csh[j * CSTR + 4 * q];
        *(float4*)&g_distT[(size_t)(n0 + j) * BDIM + m0 + 4 * q] = v;
    }
}

// ---------------- loss: min/max-normalized packed histogram ----------------
// exclusive scan of (int, float) pairs across 512 threads
__device__ __forceinline__ void exscan_cf(int v, float f, int tid, int* sci,
                                          float* scf, int& oc, float& of,
                                          int& tc, float& tf2) {
    int lane = tid & 31, w = tid >> 5;
    int xc = v; float xf = f;
    for (int o = 1; o < 32; o <<= 1) {
        int t = __shfl_up_sync(0xffffffffu, xc, o);
        float tt = __shfl_up_sync(0xffffffffu, xf, o);
        if (lane >= o) { xc += t; xf += tt; }
    }
    if (lane == 31) { sci[w] = xc; scf[w] = xf; }
    __syncthreads();
    if (tid < 32) {
        int wc = (tid < 16) ? sci[tid] : 0;
        float wf = (tid < 16) ? scf[tid] : 0.f;
        for (int o = 1; o < 16; o <<= 1) {
            int t = __shfl_up_sync(0xffffffffu, wc, o);
            float tt = __shfl_up_sync(0xffffffffu, wf, o);
            if (lane >= o) { wc += t; wf += tt; }
        }
        if (tid < 16) { sci[tid] = wc; scf[tid] = wf; }
    }
    __syncthreads();
    int offc = (w > 0) ? sci[w - 1] : 0;
    float offf = (w > 0) ? scf[w - 1] : 0.f;
    oc = offc + xc - v;
    of = offf + xf - f;
    tc = sci[15];          // grand totals
    tf2 = scf[15];
    __syncthreads();
}

__global__ __launch_bounds__(512)
void loss_kernel(float* __restrict__ out) {
    __shared__ unsigned long long hist[NBINS];   // 32KB packed (cnt<<42)|sum_q
    __shared__ int   sci[16];
    __shared__ float scf[16];
    __shared__ float wmn[16], wmx[16];
    __shared__ float slo, shi, spos;
    __shared__ int   sb1, sCb;
    __shared__ float sSb;

    const int which = blockIdx.y;
    const float* dmat = which ? g_distT : g_dist;
    const int r   = blockIdx.x;
    const int tid = threadIdx.x;

    for (int i = tid; i < NBINS; i += 512) hist[i] = 0ull;

    // load 8 elements into registers; track min/max excluding diagonal
    const float4* src = (const float4*)(dmat + (size_t)r * BDIM);
    float4 va = src[tid], vb = src[tid + 512];
    float d[8] = {va.x, va.y, va.z, va.w, vb.x, vb.y, vb.z, vb.w};
    const int i0 = tid * 4, i1 = (tid + 512) * 4;
    float mn = 1e30f, mx = -1e30f;
#pragma unroll
    for (int e = 0; e < 4; e++) {
        if (i0 + e != r) { mn = fminf(mn, d[e]); mx = fmaxf(mx, d[e]); }
        if (i1 + e != r) { mn = fminf(mn, d[4 + e]); mx = fmaxf(mx, d[4 + e]); }
    }
    for (int o = 16; o; o >>= 1) {
        mn = fminf(mn, __shfl_down_sync(0xffffffffu, mn, o));
        mx = fmaxf(mx, __shfl_down_sync(0xffffffffu, mx, o));
    }
    int lane = tid & 31, w = tid >> 5;
    if (lane == 0) { wmn[w] = mn; wmx[w] = mx; }
    if (tid == 0) spos = dmat[(size_t)r * BDIM + r];
    __syncthreads();
    if (tid == 0) {
        float a = 1e30f, b = -1e30f;
        for (int i = 0; i < 16; i++) { a = fminf(a, wmn[i]); b = fmaxf(b, wmx[i]); }
        slo = a; shi = b;
    }
    __syncthreads();

    const float thr = spos + MARGIN;
    const float lo  = slo;
    const float rng = fmaxf(shi - lo, 1e-3f) * 1.000002f;
    const float inv_w = (float)NBINS / rng;

    // bin pass: one packed 64-bit shared atomic per qualifying element
#pragma unroll
    for (int e = 0; e < 8; e++) {
        int idx = (e < 4) ? i0 + e : i1 + (e - 4);
        float dd = d[e];
        if (idx != r && dd < thr) {
            int bin = (int)((dd - lo) * inv_w);
            bin = bin < 0 ? 0 : (bin > NBINS - 1 ? NBINS - 1 : bin);
            unsigned long long pk =
                (1ull << 42) + (unsigned long long)(dd * QPOW);
            atomicAdd(&hist[bin], pk);
        }
    }
    __syncthreads();

    // scan 8 bins/thread: counts + quantized sums
    const int base = tid * (NBINS / 512);
    int lc = 0; float ls = 0.f;
    int cnt8[8];
    float sum8[8];
#pragma unroll
    for (int j = 0; j < 8; j++) {
        unsigned long long h = hist[base + j];
        cnt8[j] = (int)(h >> 42);
        sum8[j] = (float)(h & ((1ull << 42) - 1ull));
        lc += cnt8[j]; ls += sum8[j];
    }
    int pc, Ctot; float ps, Dq;
    exscan_cf(lc, ls, tid, sci, scf, pc, ps, Ctot, Dq);

    if (Ctot <= KSEL) {
        if (tid == 0) {
            float loss = (float)Ctot * thr - Dq * QINV;
            atomicAdd(&out[which], loss * SCALE);
        }
        return;
    }

    if (pc < KSEL && KSEL <= pc + lc) {
        int c = pc; float s = ps;
#pragma unroll
        for (int j = 0; j < 8; j++) {
            if (c + cnt8[j] >= KSEL) { sb1 = base + j; sCb = c; sSb = s; break; }
            c += cnt8[j]; s += sum8[j];
        }
    }
    __syncthreads();
    if (tid == 0) {
        float tstar = lo + (float)sb1 * (rng / (float)NBINS);
        float ssel = sSb * QINV + (float)(KSEL - sCb) * tstar;
        float loss = (float)KSEL * thr - ssel;
        atomicAdd(&out[which], loss * SCALE);
    }
}

// ---------------- host: tensormap building --------------------------------
typedef CUresult (*EncFn)(CUtensorMap*, CUtensorMapDataType, cuuint32_t, void*,
                          const cuuint64_t*, const cuuint64_t*, const cuuint32_t*,
                          const cuuint32_t*, CUtensorMapInterleave,
                          CUtensorMapSwizzle, CUtensorMapL2promotion,
                          CUtensorMapFloatOOBfill);

static void build_map_h(CUtensorMap* tm, void* ptr) {
    static EncFn enc = nullptr;
    if (!enc) {
        cudaDriverEntryPointQueryResult qr;
#if CUDART_VERSION >= 12050
        cudaGetDriverEntryPointByVersion("cuTensorMapEncodeTiled", (void**)&enc,
                                         12000, cudaEnableDefault, &qr);
#else
        cudaGetDriverEntryPoint("cuTensorMapEncodeTiled", (void**)&enc,
                                cudaEnableDefault, &qr);
#endif
    }
    cuuint64_t dims[2] = {DDIM, BDIM};
    cuuint64_t strides[1] = {DDIM * sizeof(__half)};
    cuuint32_t box[2] = {BK, GM};
    cuuint32_t es[2] = {1, 1};
    enc(tm, CU_TENSOR_MAP_DATA_TYPE_UINT16, 2, ptr, dims, strides, box,
        es, CU_TENSOR_MAP_INTERLEAVE_NONE, CU_TENSOR_MAP_SWIZZLE_128B,
        CU_TENSOR_MAP_L2_PROMOTION_L2_128B, CU_TENSOR_MAP_FLOAT_OOB_FILL_NONE);
}

// ---------------- launch ---------------------------------------------------
extern "C" void kernel_launch(void* const* d_in, const int* in_sizes, int n_in,
                              void* d_out, int out_size) {
    const float* x = (const float*)d_in[0];
    const float* y = (const float*)d_in[1];
    float* out = (float*)d_out;

    static CUtensorMap tmx, tmy;
    void *pxh = nullptr, *pyh = nullptr;
    cudaGetSymbolAddress(&pxh, g_xh);
    cudaGetSymbolAddress(&pyh, g_yh);
    build_map_h(&tmx, pxh);
    build_map_h(&tmy, pyh);

    cudaFuncSetAttribute(gemm_dist_kernel,
                         cudaFuncAttributeMaxDynamicSharedMemorySize, GSMEM);

    zero_out_kernel<<<1, 32>>>(out);
    rowconv_kernel<<<dim3(BDIM, 2), 256>>>(x, y);
    gemm_dist_kernel<<<dim3(BDIM / GN, BDIM / GM), 128, GSMEM>>>(tmx, tmy);
    loss_kernel<<<dim3(BDIM, 2), 512>>>(out);
}